// round 1
// baseline (speedup 1.0000x reference)
#include <cuda_runtime.h>

#define NPTS 16384
#define DIM  64
#define RT   128   // rows per CTA
#define CT   128   // cols per tile
#define NT   256   // threads per CTA
#define BSTRIDE 130  // Bs float stride per k (pad keeps 8B align: 520 bytes)

// smem layout: AsD (64*128 ull = 64KB) | Bs (64*130 float = 33280B) | sqs (128 float)
#define ASD_BYTES (DIM * RT * 8)
#define BS_BYTES  (DIM * BSTRIDE * 4)
#define SQS_BYTES (CT * 4)
#define SMEM_BYTES (ASD_BYTES + BS_BYTES + SQS_BYTES)

__device__ float g_sq[NPTS];

// ---------------- squared norms: one warp per row ----------------
__global__ void sq_kernel(const float* __restrict__ X) {
    int warp = (blockIdx.x * blockDim.x + threadIdx.x) >> 5;
    int lane = threadIdx.x & 31;
    if (warp >= NPTS) return;
    const float* row = X + (size_t)warp * DIM;
    float a = row[lane];
    float b = row[lane + 32];
    float s = a * a + b * b;
    #pragma unroll
    for (int o = 16; o; o >>= 1) s += __shfl_xor_sync(0xffffffffu, s, o);
    if (lane == 0) g_sq[warp] = s;
}

// ---------------- helpers ----------------
__device__ __forceinline__ unsigned long long dup2(float x) {
    float2 t = make_float2(x, x);
    return *reinterpret_cast<unsigned long long*>(&t);
}
__device__ __forceinline__ void ffma2(unsigned long long& d,
                                      unsigned long long a,
                                      unsigned long long b) {
    asm("fma.rn.f32x2 %0, %1, %2, %0;" : "+l"(d) : "l"(a), "l"(b));
}

// Bs physical layout (float index within a k-row):
//   col j -> ((j>>1)&3)*32 + (j>>3)*2 + (j&1)
// so the inner-loop ull load for (tx, m) sits at  m*32 + tx*2  (128B-contiguous per warp).

__global__ void __launch_bounds__(NT, 1)
knn_kernel(const float* __restrict__ X, float* __restrict__ out) {
    extern __shared__ char smem[];
    unsigned long long* AsD = (unsigned long long*)smem;
    float* Bs  = (float*)(smem + ASD_BYTES);
    float* sqs = (float*)(smem + ASD_BYTES + BS_BYTES);

    const int tid = threadIdx.x;
    const int tx  = tid & 15;        // col group
    const int ty  = tid >> 4;        // row group
    const int row0 = blockIdx.x * RT;

    // ---- load A tile (128 rows x 64), store duplicated (a,a) pairs, k-major ----
    {
        const float4* src = (const float4*)(X + (size_t)row0 * DIM);
        #pragma unroll
        for (int it = 0; it < 8; it++) {
            int q = it * NT + tid;           // 0..2047, 16 float4 per row
            int r  = q >> 4;
            int kq = (q & 15) << 2;
            float4 v = src[q];
            AsD[(kq + 0) * RT + r] = dup2(v.x);
            AsD[(kq + 1) * RT + r] = dup2(v.y);
            AsD[(kq + 2) * RT + r] = dup2(v.z);
            AsD[(kq + 3) * RT + r] = dup2(v.w);
        }
    }

    // per-thread row norms
    float sqa[8];
    #pragma unroll
    for (int r = 0; r < 8; r++) sqa[r] = g_sq[row0 + ty * 8 + r];

    float mn[8];
    int   mi[8];
    #pragma unroll
    for (int r = 0; r < 8; r++) { mn[r] = 3.402823466e38f; mi[r] = 0; }

    // prefetch tile 0
    const float4* Xf4 = (const float4*)X;
    float4 pf[8];
    #pragma unroll
    for (int it = 0; it < 8; it++) pf[it] = Xf4[it * NT + tid];

    const float4 z4 = make_float4(0.f, 0.f, 0.f, 0.f);

    for (int t = 0; t < NPTS / CT; t++) {
        // ---- store prefetched B tile into permuted k-major smem ----
        #pragma unroll
        for (int it = 0; it < 8; it++) {
            int q = it * NT + tid;
            int j  = q >> 4;
            int kq = (q & 15) << 2;
            int fj = ((j >> 1) & 3) * 32 + ((j >> 3) << 1) + (j & 1);
            float4 v = pf[it];
            Bs[(kq + 0) * BSTRIDE + fj] = v.x;
            Bs[(kq + 1) * BSTRIDE + fj] = v.y;
            Bs[(kq + 2) * BSTRIDE + fj] = v.z;
            Bs[(kq + 3) * BSTRIDE + fj] = v.w;
        }
        if (tid < CT) sqs[tid] = g_sq[t * CT + tid];
        __syncthreads();

        // col norms for this thread's 8 columns
        float sqb[8];
        #pragma unroll
        for (int c = 0; c < 8; c++) sqb[c] = sqs[tx * 8 + c];

        // prefetch next B tile (hidden under compute)
        if (t + 1 < NPTS / CT) {
            size_t base = (size_t)(t + 1) * (CT * (DIM / 4));
            #pragma unroll
            for (int it = 0; it < 8; it++) pf[it] = Xf4[base + it * NT + tid];
        }

        // ---- 8x8 micro-tile GEMM over k=64 with packed f32x2 FMA ----
        unsigned long long acc[8][4];
        #pragma unroll
        for (int r = 0; r < 8; r++)
            #pragma unroll
            for (int m = 0; m < 4; m++) acc[r][m] = 0ull;

        #pragma unroll 16
        for (int k = 0; k < DIM; k++) {
            unsigned long long a[8];
            *(ulonglong2*)&a[0] = *(const ulonglong2*)&AsD[k * RT + ty * 8 + 0];
            *(ulonglong2*)&a[2] = *(const ulonglong2*)&AsD[k * RT + ty * 8 + 2];
            *(ulonglong2*)&a[4] = *(const ulonglong2*)&AsD[k * RT + ty * 8 + 4];
            *(ulonglong2*)&a[6] = *(const ulonglong2*)&AsD[k * RT + ty * 8 + 6];
            unsigned long long b[4];
            #pragma unroll
            for (int m = 0; m < 4; m++)
                b[m] = *(const unsigned long long*)&Bs[k * BSTRIDE + m * 32 + tx * 2];
            #pragma unroll
            for (int r = 0; r < 8; r++)
                #pragma unroll
                for (int m = 0; m < 4; m++)
                    ffma2(acc[r][m], a[r], b[m]);
        }

        // ---- argmin update (mimic ref rounding: fl(fl(sq_i+sq_j) - 2*dot)) ----
        int jbase = t * CT + tx * 8;
        #pragma unroll
        for (int r = 0; r < 8; r++) {
            int ig = row0 + ty * 8 + r;
            float sa = sqa[r];
            #pragma unroll
            for (int m = 0; m < 4; m++) {
                uint2 u = *reinterpret_cast<uint2*>(&acc[r][m]);
                float d0 = __uint_as_float(u.x);
                float d1 = __uint_as_float(u.y);
                int j0 = jbase + 2 * m;
                int j1 = j0 + 1;
                float v0 = fmaf(-2.0f, d0, sa + sqb[2 * m]);
                float v1 = fmaf(-2.0f, d1, sa + sqb[2 * m + 1]);
                if (j0 != ig && v0 < mn[r]) { mn[r] = v0; mi[r] = j0; }
                if (j1 != ig && v1 < mn[r]) { mn[r] = v1; mi[r] = j1; }
            }
        }

        // ---- fused zero-fill of this CTA's 128x128 output tile ----
        #pragma unroll
        for (int it = 0; it < 16; it++) {
            int p  = it * NT + tid;      // 0..4095 float4s
            int rr = p >> 5;
            int cc = (p & 31) << 2;
            *(float4*)(out + (size_t)(row0 + rr) * NPTS + (size_t)t * CT + cc) = z4;
        }

        __syncthreads();   // before Bs is overwritten next tile
    }

    // ---- cross-thread reduction per row (tie-break: smaller index) ----
    float* redv = (float*)smem;
    int*   redi = (int*)(smem + RT * 16 * 4);
    #pragma unroll
    for (int r = 0; r < 8; r++) {
        redv[(ty * 8 + r) * 16 + tx] = mn[r];
        redi[(ty * 8 + r) * 16 + tx] = mi[r];
    }
    __syncthreads();
    if (tid < RT) {
        float bv = redv[tid * 16];
        int   bi = redi[tid * 16];
        #pragma unroll
        for (int x = 1; x < 16; x++) {
            float v = redv[tid * 16 + x];
            int   i = redi[tid * 16 + x];
            if (v < bv || (v == bv && i < bi)) { bv = v; bi = i; }
        }
        size_t rg = row0 + tid;
        out[rg * NPTS + rg] = 1.0f;   // self (always rank-1 in reference)
        out[rg * NPTS + bi] = 1.0f;   // nearest neighbor
    }
}

extern "C" void kernel_launch(void* const* d_in, const int* in_sizes, int n_in,
                              void* d_out, int out_size) {
    const float* X = (const float*)d_in[0];
    float* out = (float*)d_out;
    cudaFuncSetAttribute(knn_kernel, cudaFuncAttributeMaxDynamicSharedMemorySize, SMEM_BYTES);
    sq_kernel<<<NPTS / 8, 256>>>(X);
    knn_kernel<<<NPTS / RT, NT, SMEM_BYTES>>>(X, out);
}

// round 2
// speedup vs baseline: 1.1141x; 1.1141x over previous
#include <cuda_runtime.h>
#include <cstdint>

#define NPTS 16384
#define DIM  64
#define RT   64          // rows per CTA
#define CT   128         // cols per tile
#define NT   256         // threads per CTA
#define NCHUNK 4         // column chunks (grid.y)
#define TILES  ((NPTS / NCHUNK) / CT)   // 32 tiles per CTA

#define AS_FLOATS (RT * DIM)            // 4096
#define BS_FLOATS (CT * DIM)            // 8192 per buffer
#define SMEM_FLOATS (AS_FLOATS + 2 * BS_FLOATS)
#define SMEM_BYTES (SMEM_FLOATS * 4)    // 81920

__device__ unsigned long long g_key[NPTS];
__device__ float g_sq[NPTS];

// ---------------- squared norms: one warp per row ----------------
__global__ void sq_kernel(const float* __restrict__ X) {
    int warp = (blockIdx.x * blockDim.x + threadIdx.x) >> 5;
    int lane = threadIdx.x & 31;
    if (warp >= NPTS) return;
    const float* row = X + (size_t)warp * DIM;
    float a = row[lane];
    float b = row[lane + 32];
    float s = a * a + b * b;
    #pragma unroll
    for (int o = 16; o; o >>= 1) s += __shfl_xor_sync(0xffffffffu, s, o);
    if (lane == 0) g_sq[warp] = s;
}

__global__ void init_kernel() {
    int i = blockIdx.x * blockDim.x + threadIdx.x;
    g_key[i] = 0xFFFFFFFFFFFFFFFFull;
}

__global__ void final_kernel(float* __restrict__ out) {
    int row = blockIdx.x * blockDim.x + threadIdx.x;
    unsigned long long k = g_key[row];
    unsigned idx = (unsigned)(k & 0xFFFFFFFFu);
    out[(size_t)row * NPTS + row] = 1.0f;
    out[(size_t)row * NPTS + idx] = 1.0f;
}

// ---------------- helpers ----------------
__device__ __forceinline__ void ffma2(unsigned long long& d,
                                      unsigned long long a,
                                      unsigned long long b) {
    asm("fma.rn.f32x2 %0, %1, %2, %0;" : "+l"(d) : "l"(a), "l"(b));
}
__device__ __forceinline__ void cp16(uint32_t dst, const void* src) {
    asm volatile("cp.async.cg.shared.global [%0], [%1], 16;" :: "r"(dst), "l"(src));
}
#define CP_COMMIT() asm volatile("cp.async.commit_group;")
#define CP_WAIT(n)  asm volatile("cp.async.wait_group %0;" :: "n"(n))

// swizzle: row-major [row][64 floats]; 16B quad q at float offset ((q ^ (row&15))<<2)

__global__ void __launch_bounds__(NT, 2)
knn_kernel(const float* __restrict__ X, float* __restrict__ out) {
    extern __shared__ float smem[];
    float* As = smem;                    // 4096 floats
    float* Bs = smem + AS_FLOATS;        // 2 x 8192 floats

    const int tid = threadIdx.x;
    const int tx  = tid & 15;            // 8 cols: j = tx + 16c
    const int ty  = tid >> 4;            // 4 rows: r = ty*4 + rr
    const int row0 = blockIdx.x * RT;
    const int col0 = blockIdx.y * (NPTS / NCHUNK);

    // ---- load A tile (64 x 64), swizzled row-major ----
    #pragma unroll
    for (int it = 0; it < 4; it++) {
        int ql = it * NT + tid;
        int r = ql >> 4, q = ql & 15;
        float4 v = *(const float4*)(X + (size_t)(row0 + r) * DIM + q * 4);
        *(float4*)(As + r * DIM + ((q ^ (r & 15)) << 2)) = v;
    }

    // ---- issue B tile 0 via cp.async ----
    {
        uint32_t sB = (uint32_t)__cvta_generic_to_shared(Bs);
        #pragma unroll
        for (int it = 0; it < 8; it++) {
            int ql = it * NT + tid;
            int j = ql >> 4, q = ql & 15;
            const float* src = X + (size_t)(col0 + j) * DIM + q * 4;
            cp16(sB + (j * DIM + ((q ^ (j & 15)) << 2)) * 4, src);
        }
        CP_COMMIT();
    }

    float sqa[4];
    #pragma unroll
    for (int r = 0; r < 4; r++) sqa[r] = g_sq[row0 + ty * 4 + r];

    float mn[4];
    int   mi[4];
    #pragma unroll
    for (int r = 0; r < 4; r++) { mn[r] = 3.402823466e38f; mi[r] = 0; }

    const float4 z4 = make_float4(0.f, 0.f, 0.f, 0.f);

    for (int t = 0; t < TILES; t++) {
        if (t + 1 < TILES) {
            uint32_t sB = (uint32_t)__cvta_generic_to_shared(Bs + ((t + 1) & 1) * BS_FLOATS);
            int cb = col0 + (t + 1) * CT;
            #pragma unroll
            for (int it = 0; it < 8; it++) {
                int ql = it * NT + tid;
                int j = ql >> 4, q = ql & 15;
                const float* src = X + (size_t)(cb + j) * DIM + q * 4;
                cp16(sB + (j * DIM + ((q ^ (j & 15)) << 2)) * 4, src);
            }
            CP_COMMIT();
            CP_WAIT(1);
        } else {
            CP_WAIT(0);
        }
        __syncthreads();

        const float* Bb = Bs + (t & 1) * BS_FLOATS;

        // ---- 4x8 micro-tile, k-paired FFMA2, over 16 k-quads ----
        unsigned long long acc[32];
        #pragma unroll
        for (int i = 0; i < 32; i++) acc[i] = 0ull;

        #pragma unroll 4
        for (int q = 0; q < 16; q++) {
            ulonglong2 av[4];
            #pragma unroll
            for (int r = 0; r < 4; r++) {
                int rl = ty * 4 + r;
                av[r] = *(const ulonglong2*)(As + rl * DIM + ((q ^ (rl & 15)) << 2));
            }
            int sw = (q ^ tx) << 2;
            #pragma unroll
            for (int h = 0; h < 2; h++) {           // two groups of 4 cols: keep regs low
                ulonglong2 bv[4];
                #pragma unroll
                for (int c = 0; c < 4; c++)
                    bv[c] = *(const ulonglong2*)(Bb + (tx + 16 * (h * 4 + c)) * DIM + sw);
                #pragma unroll
                for (int r = 0; r < 4; r++)
                    #pragma unroll
                    for (int c = 0; c < 4; c++) {
                        ffma2(acc[r * 8 + h * 4 + c], av[r].x, bv[c].x);
                        ffma2(acc[r * 8 + h * 4 + c], av[r].y, bv[c].y);
                    }
            }
        }

        // ---- argmin update (dist = fl(fl(sa+sb) - 2*dot)) ----
        int jb = col0 + t * CT + tx;
        #pragma unroll
        for (int c = 0; c < 8; c++) {
            int j = jb + 16 * c;
            float sb = __ldg(&g_sq[j]);
            #pragma unroll
            for (int r = 0; r < 4; r++) {
                uint2 p = *(uint2*)&acc[r * 8 + c];
                float dot = __uint_as_float(p.x) + __uint_as_float(p.y);
                float v = fmaf(-2.0f, dot, sqa[r] + sb);
                int ig = row0 + ty * 4 + r;
                if (j != ig && v < mn[r]) { mn[r] = v; mi[r] = j; }
            }
        }

        // ---- fused zero-fill of this 64x128 output tile ----
        #pragma unroll
        for (int i = 0; i < 2; i++) {
            int p  = i * NT + tid;          // 0..511 float4s
            int rr = p >> 3;
            int cc = (p & 7) << 2;
            *(float4*)(out + (size_t)(row0 + rr) * NPTS + (size_t)(col0 + t * CT) + cc) = z4;
        }

        __syncthreads();
    }

    // ---- merge across tx (16 partials per row), then cross-CTA atomicMin ----
    __syncthreads();
    float* redv = smem;                          // reuse As region (8KB needed)
    int*   redi = (int*)(smem + RT * 16);
    #pragma unroll
    for (int r = 0; r < 4; r++) {
        int idx = (ty * 4 + r) * 16 + tx;
        redv[idx] = mn[r];
        redi[idx] = mi[r];
    }
    __syncthreads();
    if (tid < RT) {
        float bv = redv[tid * 16];
        int   bi = redi[tid * 16];
        #pragma unroll
        for (int x = 1; x < 16; x++) {
            float v = redv[tid * 16 + x];
            int   i = redi[tid * 16 + x];
            if (v < bv || (v == bv && i < bi)) { bv = v; bi = i; }
        }
        unsigned long long key =
            ((unsigned long long)__float_as_uint(bv) << 32) | (unsigned)bi;
        atomicMin(&g_key[row0 + tid], key);
    }
}

extern "C" void kernel_launch(void* const* d_in, const int* in_sizes, int n_in,
                              void* d_out, int out_size) {
    const float* X = (const float*)d_in[0];
    float* out = (float*)d_out;
    cudaFuncSetAttribute(knn_kernel, cudaFuncAttributeMaxDynamicSharedMemorySize, SMEM_BYTES);
    sq_kernel<<<NPTS / 8, 256>>>(X);
    init_kernel<<<NPTS / 256, 256>>>();
    knn_kernel<<<dim3(NPTS / RT, NCHUNK), NT, SMEM_BYTES>>>(X, out);
    final_kernel<<<NPTS / 256, 256>>>(out);
}

// round 4
// speedup vs baseline: 1.2532x; 1.1249x over previous
#include <cuda_runtime.h>
#include <cstdint>

#define NPTS 16384
#define DIM  64
#define MB   256                  // rows per CTA
#define NBT  128                  // cols per tile
#define NT   256                  // threads
#define NCHUNK 2
#define COLS_PER_CTA (NPTS / NCHUNK)     // 8192
#define TILES (COLS_PER_CTA / NBT)       // 64
#define RS   68                   // padded smem row stride (floats)

// smem (floats): A0 | A1 | B[2] | sqs
#define OFF_A0 0
#define OFF_A1 (MB * RS)                       // 17408
#define OFF_B  (2 * MB * RS)                   // 34816
#define BBUF   (NBT * RS)                      // 8704
#define OFF_SQ (OFF_B + 2 * BBUF)              // 52224
#define SMEM_FLOATS (OFF_SQ + NBT)
#define SMEM_BYTES (SMEM_FLOATS * 4)           // 209408

__device__ float g_t0[(size_t)NPTS * DIM];
__device__ float g_t1[(size_t)NPTS * DIM];
__device__ float g_sq[NPTS];
__device__ unsigned long long g_key[NPTS];

// ---------------- helpers ----------------
__device__ __forceinline__ uint32_t cvt_tf32(float x) {
    uint32_t u;
    asm("cvt.rna.tf32.f32 %0, %1;" : "=r"(u) : "f"(x));
    return u;
}
__device__ __forceinline__ void cp16(uint32_t dst, const void* src) {
    asm volatile("cp.async.cg.shared.global [%0], [%1], 16;" :: "r"(dst), "l"(src));
}
#define CP_COMMIT() asm volatile("cp.async.commit_group;")
#define CP_WAIT(n)  asm volatile("cp.async.wait_group %0;" :: "n"(n))

#define MMA(c, a, b) \
    asm volatile("mma.sync.aligned.m16n8k8.row.col.f32.tf32.tf32.f32 " \
        "{%0,%1,%2,%3},{%4,%5,%6,%7},{%8,%9},{%0,%1,%2,%3};" \
        : "+f"((c)[0]), "+f"((c)[1]), "+f"((c)[2]), "+f"((c)[3]) \
        : "r"((a)[0]), "r"((a)[1]), "r"((a)[2]), "r"((a)[3]), \
          "r"((b)[0]), "r"((b)[1]))

// ---------------- small kernels ----------------
__global__ void sq_kernel(const float* __restrict__ X) {
    int warp = (blockIdx.x * blockDim.x + threadIdx.x) >> 5;
    int lane = threadIdx.x & 31;
    if (warp >= NPTS) return;
    const float* row = X + (size_t)warp * DIM;
    float a = row[lane], b = row[lane + 32];
    float s = a * a + b * b;
    #pragma unroll
    for (int o = 16; o; o >>= 1) s += __shfl_xor_sync(0xffffffffu, s, o);
    if (lane == 0) g_sq[warp] = s;
}

__global__ void prep_kernel(const float* __restrict__ X) {
    int idx = blockIdx.x * blockDim.x + threadIdx.x;
    float x = X[idx];
    uint32_t u0 = cvt_tf32(x);
    float f0 = __uint_as_float(u0);
    uint32_t u1 = cvt_tf32(x - f0);
    g_t0[idx] = f0;
    g_t1[idx] = __uint_as_float(u1);
}

__global__ void init_kernel() {
    g_key[blockIdx.x * blockDim.x + threadIdx.x] = 0xFFFFFFFFFFFFFFFFull;
}

__global__ void final_kernel(float* __restrict__ out) {
    int row = blockIdx.x * blockDim.x + threadIdx.x;
    unsigned idx = (unsigned)(g_key[row] & 0xFFFFFFFFu);
    out[(size_t)row * NPTS + row] = 1.0f;
    out[(size_t)row * NPTS + idx] = 1.0f;
}

// ---------------- main kernel ----------------
__global__ void __launch_bounds__(NT, 1)
knn_kernel(const float* __restrict__ X, float* __restrict__ out) {
    extern __shared__ float sm[];
    uint32_t smb;
    asm("{ .reg .u64 t; cvta.to.shared.u64 t, %1; cvt.u32.u64 %0, t; }"
        : "=r"(smb) : "l"(sm));

    const int tid  = threadIdx.x;
    const int lane = tid & 31;
    const int wid  = tid >> 5;
    const int wm   = wid >> 1;          // 0..3 -> rows wm*64
    const int wn   = wid & 1;           // 0..1 -> cols wn*64
    const int lg   = lane >> 2;         // group id 0..7
    const int lt   = lane & 3;          // thread-in-group
    const int row0 = blockIdx.x * MB;
    const int col0 = blockIdx.y * COLS_PER_CTA;

    // ---- group 0: A planes + B tile 0 ----
    #pragma unroll
    for (int i = 0; i < 16; i++) {
        int idx = i * NT + tid;
        int r = idx >> 4, q = idx & 15;
        cp16(smb + (OFF_A0 + r * RS) * 4 + q * 16, &g_t0[(size_t)(row0 + r) * DIM + q * 4]);
        cp16(smb + (OFF_A1 + r * RS) * 4 + q * 16, &g_t1[(size_t)(row0 + r) * DIM + q * 4]);
    }
    #pragma unroll
    for (int i = 0; i < 8; i++) {
        int idx = i * NT + tid;
        int r = idx >> 4, q = idx & 15;
        cp16(smb + (OFF_B + r * RS) * 4 + q * 16, &X[(size_t)(col0 + r) * DIM + q * 4]);
    }
    CP_COMMIT();
    // ---- group 1: B tile 1 ----
    #pragma unroll
    for (int i = 0; i < 8; i++) {
        int idx = i * NT + tid;
        int r = idx >> 4, q = idx & 15;
        cp16(smb + (OFF_B + BBUF + r * RS) * 4 + q * 16, &X[(size_t)(col0 + NBT + r) * DIM + q * 4]);
    }
    CP_COMMIT();

    const uint32_t* A0u = (const uint32_t*)(sm + OFF_A0);
    const uint32_t* A1u = (const uint32_t*)(sm + OFF_A1);
    float* sqs = sm + OFF_SQ;

    float mn[8];
    int   mi[8];
    #pragma unroll
    for (int s = 0; s < 8; s++) { mn[s] = 3.402823466e38f; mi[s] = 0; }

    const int abase = (wm * 64 + lg) * RS + lt;   // + mf*16*RS (+8*RS) + kb (+4)

    for (int t = 0; t < TILES; t++) {
        const float* Bs = sm + OFF_B + (t & 1) * BBUF;
        const int cb = col0 + t * NBT;

        if (tid < NBT) sqs[tid] = g_sq[cb + tid];
        if (t + 1 < TILES) { CP_WAIT(1); } else { CP_WAIT(0); }
        __syncthreads();

        float acc[4][8][4];
        #pragma unroll
        for (int mf = 0; mf < 4; mf++)
            #pragma unroll
            for (int nf = 0; nf < 8; nf++)
                #pragma unroll
                for (int r = 0; r < 4; r++) acc[mf][nf][r] = 0.f;

        #pragma unroll
        for (int k8 = 0; k8 < 8; k8++) {
            const int kb = k8 * 8;
            uint32_t ta0[4][4], ta1[4][4];
            #pragma unroll
            for (int mf = 0; mf < 4; mf++) {
                int b = abase + mf * 16 * RS + kb;
                ta0[mf][0] = A0u[b];
                ta0[mf][1] = A0u[b + 8 * RS];
                ta0[mf][2] = A0u[b + 4];
                ta0[mf][3] = A0u[b + 8 * RS + 4];
                ta1[mf][0] = A1u[b];
                ta1[mf][1] = A1u[b + 8 * RS];
                ta1[mf][2] = A1u[b + 4];
                ta1[mf][3] = A1u[b + 8 * RS + 4];
            }
            uint32_t u0[8][2], u1[8][2];
            #pragma unroll
            for (int nf = 0; nf < 8; nf++) {
                int cbs = (wn * 64 + nf * 8 + lg) * RS + kb + lt;
                float b0 = Bs[cbs];
                float b1 = Bs[cbs + 4];
                u0[nf][0] = cvt_tf32(b0);
                u1[nf][0] = cvt_tf32(b0 - __uint_as_float(u0[nf][0]));
                u0[nf][1] = cvt_tf32(b1);
                u1[nf][1] = cvt_tf32(b1 - __uint_as_float(u0[nf][1]));
            }
            // product-major: same-acc reuse distance = 32 mma
            #pragma unroll
            for (int mf = 0; mf < 4; mf++)
                #pragma unroll
                for (int nf = 0; nf < 8; nf++) MMA(acc[mf][nf], ta0[mf], u0[nf]);
            #pragma unroll
            for (int mf = 0; mf < 4; mf++)
                #pragma unroll
                for (int nf = 0; nf < 8; nf++) MMA(acc[mf][nf], ta0[mf], u1[nf]);
            #pragma unroll
            for (int mf = 0; mf < 4; mf++)
                #pragma unroll
                for (int nf = 0; nf < 8; nf++) MMA(acc[mf][nf], ta1[mf], u0[nf]);
        }

        // ---- epilogue: argmin of (sb - 2*dot); self excluded ----
        #pragma unroll
        for (int mf = 0; mf < 4; mf++) {
            const int ig = row0 + wm * 64 + mf * 16 + lg;   // row of slot h=0; +8 for h=1
            #pragma unroll
            for (int nf = 0; nf < 8; nf++) {
                const int lc = wn * 64 + nf * 8 + 2 * lt;
                const float sb0 = sqs[lc], sb1 = sqs[lc + 1];
                const int j0 = cb + lc, j1 = j0 + 1;
                float v;
                v = fmaf(-2.f, acc[mf][nf][0], sb0);
                if (j0 != ig && v < mn[mf * 2]) { mn[mf * 2] = v; mi[mf * 2] = j0; }
                v = fmaf(-2.f, acc[mf][nf][1], sb1);
                if (j1 != ig && v < mn[mf * 2]) { mn[mf * 2] = v; mi[mf * 2] = j1; }
                v = fmaf(-2.f, acc[mf][nf][2], sb0);
                if (j0 != ig + 8 && v < mn[mf * 2 + 1]) { mn[mf * 2 + 1] = v; mi[mf * 2 + 1] = j0; }
                v = fmaf(-2.f, acc[mf][nf][3], sb1);
                if (j1 != ig + 8 && v < mn[mf * 2 + 1]) { mn[mf * 2 + 1] = v; mi[mf * 2 + 1] = j1; }
            }
        }

        // ---- fused zero-fill: warp wid owns rows wid*32..+31, 512B/row wavefront ----
        {
            const float4 z4 = make_float4(0.f, 0.f, 0.f, 0.f);
            float4* p = (float4*)(out + (size_t)(row0 + wid * 32) * NPTS + cb) + lane;
            #pragma unroll 8
            for (int i = 0; i < 32; i++) {
                *p = z4;
                p += NPTS / 4;
            }
        }

        __syncthreads();
        if (t + 2 < TILES) {
            #pragma unroll
            for (int i = 0; i < 8; i++) {
                int idx = i * NT + tid;
                int r = idx >> 4, q = idx & 15;
                cp16(smb + (OFF_B + (t & 1) * BBUF + r * RS) * 4 + q * 16,
                     &X[(size_t)(col0 + (t + 2) * NBT + r) * DIM + q * 4]);
            }
            CP_COMMIT();
        }
    }

    // ---- publish per-row results (monotonic float->uint map handles negatives) ----
    #pragma unroll
    for (int s = 0; s < 8; s++) {
        int row = row0 + wm * 64 + (s >> 1) * 16 + lg + (s & 1) * 8;
        uint32_t b = __float_as_uint(mn[s]);
        b ^= (uint32_t)(((int32_t)b >> 31)) | 0x80000000u;
        unsigned long long key = ((unsigned long long)b << 32) | (unsigned)mi[s];
        atomicMin(&g_key[row], key);
    }
}

extern "C" void kernel_launch(void* const* d_in, const int* in_sizes, int n_in,
                              void* d_out, int out_size) {
    const float* X = (const float*)d_in[0];
    float* out = (float*)d_out;
    cudaFuncSetAttribute(knn_kernel, cudaFuncAttributeMaxDynamicSharedMemorySize, SMEM_BYTES);
    sq_kernel<<<NPTS / 8, 256>>>(X);
    prep_kernel<<<NPTS * DIM / 256, 256>>>(X);
    init_kernel<<<NPTS / 256, 256>>>();
    knn_kernel<<<dim3(NPTS / MB, NCHUNK), NT, SMEM_BYTES>>>(X, out);
    final_kernel<<<NPTS / 256, 256>>>(out);
}